// round 12
// baseline (speedup 1.0000x reference)
#include <cuda_runtime.h>
#include <math.h>

// Problem sizes
#define Bz 32
#define Sz 512
#define Iz 128
#define Hz 1024
#define Oz 128
#define TPB 256
#define TPBS 512
#define SCAN_GRID 128

typedef unsigned long long u64;

// Scratch (device globals)
__device__ __align__(16) float g_gates[(size_t)3 * Sz * Hz * Bz];   // [gate][t][j][b]
__device__ __align__(16) float g_seq[(size_t)Sz * Hz * Bz];         // paired: [t][j/2][b][2]
__device__ __align__(16) float g_h[Hz * Bz];   // paired: [j/2][b][2]
__device__ __align__(16) float g_u[Hz * Bz];   // paired
__device__ int   g_bar[2 * Sz];
__device__ int   g_flag[2 * Sz];

__device__ __forceinline__ float sigmoidf_(float x) {
    return 1.0f / (1.0f + expf(-x));
}

// packed fp32x2 FMA: acc = a * b + acc
__device__ __forceinline__ void ffma2(u64& acc, u64 a, u64 b) {
    asm("fma.rn.f32x2 %0, %1, %2, %0;" : "+l"(acc) : "l"(a), "l"(b));
}
__device__ __forceinline__ float f2sum(u64 v) {
    float lo, hi;
    asm("mov.b64 {%0, %1}, %2;" : "=f"(lo), "=f"(hi) : "l"(v));
    return lo + hi;
}

// Fence-free grid barrier: release-atomic arrive, single-writer release flag,
// acquire spin with nanosleep backoff.
__device__ __forceinline__ void grid_bar(int i, int ncta) {
    __syncthreads();
    if (threadIdx.x == 0) {
        int v;
        asm volatile("atom.release.gpu.global.add.s32 %0, [%1], 1;"
                     : "=r"(v) : "l"(&g_bar[i]) : "memory");
        if (v == ncta - 1) {
            asm volatile("st.release.gpu.global.s32 [%0], 1;"
                         :: "l"(&g_flag[i]) : "memory");
        } else {
            int f;
            for (;;) {
                asm volatile("ld.acquire.gpu.global.s32 %0, [%1];"
                             : "=r"(f) : "l"(&g_flag[i]) : "memory");
                if (f) break;
                __nanosleep(64);
            }
        }
    }
    __syncthreads();
}

// ---------------------------------------------------------------------------
// prep: init h state (paired layout) + zero barrier counters/flags
// ---------------------------------------------------------------------------
__global__ void prep_kernel(const float* __restrict__ h0, int layer) {
    int idx = blockIdx.x * TPB + threadIdx.x;
    int j = idx >> 5;
    int b = idx & 31;
    g_h[(j >> 1) * 64 + 2 * b + (j & 1)] = h0[b * (2 * Hz) + layer * Hz + j];
    if (idx < 2 * Sz) { g_bar[idx] = 0; g_flag[idx] = 0; }
}

// ---------------------------------------------------------------------------
// proj0 v2: layer-0 input projections (K=128). s-pair blocking + FFMA2.
// ---------------------------------------------------------------------------
__global__ void __launch_bounds__(TPBS, 1) proj0_kernel(
    const float* __restrict__ x,
    const float* __restrict__ Wz, const float* __restrict__ Wr, const float* __restrict__ Wg)
{
    __shared__ float xraw[2 * 32 * 132];   // [s2][b][i] pitch 132
    __shared__ float xs[2 * 4096];         // paired [s2][ip=64][b][2]
    const int rb = blockIdx.x;
    const int sp = blockIdx.y;
    const int s0 = 2 * sp;
    const int tid = threadIdx.x, lane = tid & 31, w = tid >> 5;

    #pragma unroll
    for (int rep = 0; rep < 4; ++rep) {
        int row = rep * 16 + w;
        int s2 = row >> 5, b = row & 31;
        float4 v = ((const float4*)(x + ((size_t)b * Sz + s0 + s2) * Iz))[lane];
        *(float4*)&xraw[(s2 * 32 + b) * 132 + 4 * lane] = v;
    }
    __syncthreads();
    #pragma unroll
    for (int rep = 0; rep < 8; ++rep) {
        int e = rep * 512 + tid;
        int b = e & 31;
        int ip = (e >> 5) & 63;
        int s2 = e >> 11;
        float lo = xraw[(s2 * 32 + b) * 132 + 2 * ip];
        float hi = xraw[(s2 * 32 + b) * 132 + 2 * ip + 1];
        ((float2*)xs)[e] = make_float2(lo, hi);
    }
    __syncthreads();

    const float* wrow[12];
    #pragma unroll
    for (int q = 0; q < 12; ++q) {
        int rr = rb * 192 + w * 12 + q;
        int g = rr >> 10, j = rr & 1023;
        const float* Wp = (g == 0) ? Wz : ((g == 1) ? Wr : Wg);
        wrow[q] = Wp + (size_t)j * Iz;
    }

    u64 a0[12], a1[12];
    #pragma unroll
    for (int q = 0; q < 12; ++q) { a0[q] = 0ull; a1[q] = 0ull; }

    const u64* h0q = (const u64*)&xs[2 * lane];
    const u64* h1q = (const u64*)&xs[4096 + 2 * lane];
    #pragma unroll 4
    for (int ii = 0; ii < 32; ++ii) {
        u64 hA0 = h0q[(2 * ii + 0) * 32];
        u64 hB0 = h0q[(2 * ii + 1) * 32];
        u64 hA1 = h1q[(2 * ii + 0) * 32];
        u64 hB1 = h1q[(2 * ii + 1) * 32];
        #pragma unroll
        for (int q = 0; q < 12; ++q) {
            ulonglong2 wq = ((const ulonglong2*)wrow[q])[ii];
            ffma2(a0[q], wq.x, hA0); ffma2(a0[q], wq.y, hB0);
            ffma2(a1[q], wq.x, hA1); ffma2(a1[q], wq.y, hB1);
        }
    }

    #pragma unroll
    for (int q = 0; q < 12; ++q) {
        int rr = rb * 192 + w * 12 + q;
        int g = rr >> 10, j = rr & 1023;
        size_t b0 = (((size_t)g * Sz + s0)     * Hz + j) * Bz + lane;
        size_t b1 = (((size_t)g * Sz + s0 + 1) * Hz + j) * Bz + lane;
        g_gates[b0] = f2sum(a0[q]);
        g_gates[b1] = f2sum(a1[q]);
    }
}

// ---------------------------------------------------------------------------
// proj1 v2: K=1024, s-pair blocking + FFMA2 (unchanged).
// ---------------------------------------------------------------------------
__global__ void __launch_bounds__(TPBS, 1) proj1_kernel(
    const float* __restrict__ Wz, const float* __restrict__ Wr, const float* __restrict__ Wg)
{
    __shared__ float xs[2 * 8192];
    const int rb = blockIdx.x;
    const int sp = blockIdx.y;
    const int s0 = 2 * sp, s1 = s0 + 1;
    const int tid = threadIdx.x, lane = tid & 31, w = tid >> 5;

    const float* wrow[12];
    #pragma unroll
    for (int q = 0; q < 12; ++q) {
        int rr = rb * 192 + w * 12 + q;
        int g = rr >> 10, j = rr & 1023;
        const float* Wp = (g == 0) ? Wz : ((g == 1) ? Wr : Wg);
        wrow[q] = Wp + (size_t)j * Hz;
    }

    u64 a0[12], a1[12];
    #pragma unroll
    for (int q = 0; q < 12; ++q) { a0[q] = 0ull; a1[q] = 0ull; }

    for (int kt = 0; kt < 4; ++kt) {
        __syncthreads();
        {
            const float4* src0 = (const float4*)&g_seq[(size_t)s0 * (Hz * Bz) + kt * 8192];
            const float4* src1 = (const float4*)&g_seq[(size_t)s1 * (Hz * Bz) + kt * 8192];
            float4* d = (float4*)xs;
            #pragma unroll
            for (int r = 0; r < 4; ++r) d[r * TPBS + tid] = src0[r * TPBS + tid];
            #pragma unroll
            for (int r = 0; r < 4; ++r) d[2048 + r * TPBS + tid] = src1[r * TPBS + tid];
        }
        __syncthreads();

        const u64* h0q = (const u64*)&xs[2 * lane];
        const u64* h1q = (const u64*)&xs[8192 + 2 * lane];
        #pragma unroll 4
        for (int ii = 0; ii < 64; ++ii) {
            u64 hA0 = h0q[(2 * ii + 0) * 32];
            u64 hB0 = h0q[(2 * ii + 1) * 32];
            u64 hA1 = h1q[(2 * ii + 0) * 32];
            u64 hB1 = h1q[(2 * ii + 1) * 32];
            #pragma unroll
            for (int q = 0; q < 12; ++q) {
                ulonglong2 wq = ((const ulonglong2*)(wrow[q] + kt * 256))[ii];
                ffma2(a0[q], wq.x, hA0); ffma2(a0[q], wq.y, hB0);
                ffma2(a1[q], wq.x, hA1); ffma2(a1[q], wq.y, hB1);
            }
        }
    }

    #pragma unroll
    for (int q = 0; q < 12; ++q) {
        int rr = rb * 192 + w * 12 + q;
        int g = rr >> 10, j = rr & 1023;
        size_t b0 = (((size_t)g * Sz + s0) * Hz + j) * Bz + lane;
        size_t b1 = (((size_t)g * Sz + s1) * Hz + j) * Bz + lane;
        g_gates[b0] = f2sum(a0[q]);
        g_gates[b1] = f2sum(a1[q]);
    }
}

// ---------------------------------------------------------------------------
// scan v9: NO smem staging. Each warp owns a 64-k slice (32 k-pairs) and
// reads h/u for it directly from L2 via __ldcg (each element consumed by
// exactly one warp -> staging bought nothing). 6 syncs/step total.
// 128 CTAs x 512 threads.
//
// SMEM (floats): ws 24576 | part 8192 = 32768 (128KB)
// ---------------------------------------------------------------------------
#define SCAN_SMEM_FLOATS (24576 + 8192)

__global__ void __launch_bounds__(TPBS, 1) scan_kernel(
    const float* __restrict__ Whz, const float* __restrict__ Whr, const float* __restrict__ Whg,
    const float* __restrict__ bz,  const float* __restrict__ br,  const float* __restrict__ bg,
    float* __restrict__ hid_out, int layer)
{
    extern __shared__ float smem[];
    float* ws   = smem;            // 24576  (z:0-7, r:8-15, g:16-23)
    float* part = smem + 24576;    // ph1: [16][16][32]; ph2: [16][8][32]

    const int tid = threadIdx.x, lane = tid & 31, w = tid >> 5;
    const int jbase = blockIdx.x * 8;
    const int ncta = (int)gridDim.x;

    // ---- preload weights (once per layer): 6144 float4 --------------------
    for (int idx = tid; idx < 6144; idx += TPBS) {
        int g  = idx >> 11;
        int r2 = idx & 2047;
        int jl = r2 >> 8;
        int k4 = r2 & 255;
        const float* W = (g == 0) ? Whz : ((g == 1) ? Whr : Whg);
        float4 v = *(const float4*)(W + (size_t)(jbase + jl) * Hz + k4 * 4);
        *(float4*)&ws[((g * 8 + jl) << 10) + k4 * 4] = v;
    }
    __syncthreads();

    const int jr = w & 7;
    const int jg = jbase + jr;
    const int bb = lane;
    const float bzj = bz[jg], brj = br[jg], bgj = bg[jg];
    const size_t plane = (size_t)Sz * Hz * Bz;
    const int pidx = (jg >> 1) * 64 + 2 * bb + (jg & 1);

    // this warp's k-slice: k-pairs [w*32, w*32+32), lane-indexed u64 view
    const u64* hp1 = (const u64*)g_h + (size_t)(w * 32) * 32 + lane;
    const u64* hp2 = (const u64*)g_u + (size_t)(w * 32) * 32 + lane;
    const int kg = w * 64;   // float offset of slice within a weight row

    for (int t = 0; t < Sz; ++t) {
        const size_t gb = ((size_t)t * Hz + jg) * Bz + bb;
        const size_t sgb = (((size_t)t * (Hz / 2) + (jg >> 1)) * Bz + bb) * 2 + (jg & 1);
        float gzv = g_gates[gb];
        float grv = g_gates[plane + gb];
        float hv  = g_h[pidx];
        float zg = 0.f;

        // ================= phase 1: z, r, u = r*h =========================
        u64 az[8], ar[8];
        #pragma unroll
        for (int q = 0; q < 8; ++q) { az[q] = 0ull; ar[q] = 0ull; }
        #pragma unroll
        for (int ii = 0; ii < 16; ++ii) {
            u64 hA = __ldcg(hp1 + (2 * ii + 0) * 32);
            u64 hB = __ldcg(hp1 + (2 * ii + 1) * 32);
            #pragma unroll
            for (int q = 0; q < 8; ++q) {
                ulonglong2 qz = ((const ulonglong2*)&ws[q * 1024 + kg])[ii];
                ulonglong2 qr = ((const ulonglong2*)&ws[(8 + q) * 1024 + kg])[ii];
                ffma2(az[q], qz.x, hA); ffma2(az[q], qz.y, hB);
                ffma2(ar[q], qr.x, hA); ffma2(ar[q], qr.y, hB);
            }
        }
        #pragma unroll
        for (int q = 0; q < 8; ++q) {
            part[(w * 16 + q) * 32 + lane]     = f2sum(az[q]);
            part[(w * 16 + 8 + q) * 32 + lane] = f2sum(ar[q]);
        }
        __syncthreads();

        // split tail: w<8 -> z gate (zg persists); w>=8 -> r gate + u store
        if (w < 8) {
            float zsum = 0.f;
            #pragma unroll
            for (int wi = 0; wi < 16; ++wi)
                zsum += part[(wi * 16 + jr) * 32 + bb];
            zg = sigmoidf_(zsum + gzv + bzj);
        } else {
            float rsum = 0.f;
            #pragma unroll
            for (int wi = 0; wi < 16; ++wi)
                rsum += part[(wi * 16 + 8 + jr) * 32 + bb];
            float rg = sigmoidf_(rsum + grv + brj);
            g_u[pidx] = rg * hv;
        }

        grid_bar(2 * t, ncta);

        float ggv = 0.f;
        if (w < 8) ggv = g_gates[2 * plane + gb];

        // ================= phase 2: g, h_new ==============================
        u64 ag[8];
        #pragma unroll
        for (int q = 0; q < 8; ++q) ag[q] = 0ull;
        #pragma unroll
        for (int ii = 0; ii < 16; ++ii) {
            u64 hA = __ldcg(hp2 + (2 * ii + 0) * 32);
            u64 hB = __ldcg(hp2 + (2 * ii + 1) * 32);
            #pragma unroll
            for (int q = 0; q < 8; ++q) {
                ulonglong2 qg = ((const ulonglong2*)&ws[(16 + q) * 1024 + kg])[ii];
                ffma2(ag[q], qg.x, hA); ffma2(ag[q], qg.y, hB);
            }
        }
        #pragma unroll
        for (int q = 0; q < 8; ++q)
            part[(w * 8 + q) * 32 + lane] = f2sum(ag[q]);
        __syncthreads();

        if (w < 8) {
            float gsum = 0.f;
            #pragma unroll
            for (int wi = 0; wi < 16; ++wi)
                gsum += part[(wi * 8 + jr) * 32 + bb];
            float gv = tanhf(gsum + ggv + bgj);
            float hn = zg * hv + (1.0f - zg) * gv;
            g_h[pidx] = hn;
            g_seq[sgb] = hn;
            if (t == Sz - 1) hid_out[bb * (2 * Hz) + layer * Hz + jg] = hn;
        }

        grid_bar(2 * t + 1, ncta);
    }
}

// ---------------------------------------------------------------------------
// projy v2 (unchanged)
// ---------------------------------------------------------------------------
__global__ void __launch_bounds__(TPB) projy_kernel(
    const float* __restrict__ Wy, const float* __restrict__ by, float* __restrict__ y)
{
    __shared__ float xs[8192];
    const int s = blockIdx.x;
    const int tid = threadIdx.x, lane = tid & 31, w = tid >> 5;

    u64 acc[16];
    #pragma unroll
    for (int q = 0; q < 16; ++q) acc[q] = 0ull;

    for (int kt = 0; kt < 4; ++kt) {
        __syncthreads();
        {
            const float4* src = (const float4*)&g_seq[(size_t)s * (Hz * Bz) + kt * 8192];
            float4* d = (float4*)xs;
            #pragma unroll
            for (int r = 0; r < 8; ++r) d[r * TPB + tid] = src[r * TPB + tid];
        }
        __syncthreads();

        const u64* hq = (const u64*)&xs[2 * lane];
        #pragma unroll 4
        for (int ii = 0; ii < 64; ++ii) {
            u64 hA = hq[(2 * ii + 0) * 32];
            u64 hB = hq[(2 * ii + 1) * 32];
            #pragma unroll
            for (int q = 0; q < 16; ++q) {
                int o = w * 16 + q;
                ulonglong2 wq = ((const ulonglong2*)(Wy + (size_t)o * Hz + kt * 256))[ii];
                ffma2(acc[q], wq.x, hA); ffma2(acc[q], wq.y, hB);
            }
        }
    }

    #pragma unroll
    for (int q = 0; q < 16; ++q) {
        int o = w * 16 + q;
        y[(size_t)lane * (Sz * Oz) + (size_t)s * Oz + o] = f2sum(acc[q]) + by[o];
    }
}

// ---------------------------------------------------------------------------
extern "C" void kernel_launch(void* const* d_in, const int* in_sizes, int n_in,
                              void* d_out, int out_size) {
    (void)in_sizes; (void)n_in; (void)out_size;
    const float* x    = (const float*)d_in[0];
    const float* h0   = (const float*)d_in[1];
    const float* Wxz0 = (const float*)d_in[2];
    const float* Whz0 = (const float*)d_in[3];
    const float* bz0  = (const float*)d_in[4];
    const float* Wxr0 = (const float*)d_in[5];
    const float* Whr0 = (const float*)d_in[6];
    const float* br0  = (const float*)d_in[7];
    const float* Wxg0 = (const float*)d_in[8];
    const float* Whg0 = (const float*)d_in[9];
    const float* bg0  = (const float*)d_in[10];
    const float* Wxz1 = (const float*)d_in[11];
    const float* Whz1 = (const float*)d_in[12];
    const float* bz1  = (const float*)d_in[13];
    const float* Wxr1 = (const float*)d_in[14];
    const float* Whr1 = (const float*)d_in[15];
    const float* br1  = (const float*)d_in[16];
    const float* Wxg1 = (const float*)d_in[17];
    const float* Whg1 = (const float*)d_in[18];
    const float* bg1  = (const float*)d_in[19];
    const float* Wy   = (const float*)d_in[20];
    const float* by   = (const float*)d_in[21];

    float* y   = (float*)d_out;
    float* hid = (float*)d_out + (size_t)Bz * Sz * Oz;

    const int scan_smem = SCAN_SMEM_FLOATS * (int)sizeof(float);
    cudaFuncSetAttribute(scan_kernel, cudaFuncAttributeMaxDynamicSharedMemorySize, scan_smem);

    // Layer 0
    proj0_kernel<<<dim3(16, Sz / 2), TPBS>>>(x, Wxz0, Wxr0, Wxg0);
    prep_kernel<<<SCAN_GRID, TPB>>>(h0, 0);
    scan_kernel<<<SCAN_GRID, TPBS, scan_smem>>>(Whz0, Whr0, Whg0, bz0, br0, bg0, hid, 0);

    // Layer 1
    proj1_kernel<<<dim3(16, Sz / 2), TPBS>>>(Wxz1, Wxr1, Wxg1);
    prep_kernel<<<SCAN_GRID, TPB>>>(h0, 1);
    scan_kernel<<<SCAN_GRID, TPBS, scan_smem>>>(Whz1, Whr1, Whg1, bz1, br1, bg1, hid, 1);

    // Output head
    projy_kernel<<<Sz, TPB>>>(Wy, by, y);
}